// round 12
// baseline (speedup 1.0000x reference)
#include <cuda_runtime.h>
#include <cuda_fp16.h>
#include <cstdint>

#define NROWS 16384
#define INDIM 768
#define DD    128
#define BN    128
#define NJT   (NROWS / BN)
#define NITEMS (128 * NJT)

// ---------------- device scratch (no allocs allowed) ----------------
__device__ float g_wvfc[DD];
__device__ float g_bu_p;
__device__ float g_bu;
__device__ float g_wu[INDIM];
__device__ float g_bqk[256];
__device__ float g_u[NROWS];   // stores 0.5*u (sig*u = uh*tanh(0.5s) + uh)
__device__ __align__(16) __half g_xhi[NROWS * INDIM];
__device__ __align__(16) __half g_wTh[256 * INDIM];
__device__ __align__(16) __half g_qf[NROWS * DD];
__device__ __align__(16) __half g_kf[NROWS * DD];

// ---------------- PTX helpers (base ISA only) -------------------------
__device__ __forceinline__ uint32_t smem_u32(const void* p) {
    uint32_t a;
    asm("{ .reg .u64 t; cvta.to.shared.u64 t, %1; cvt.u32.u64 %0, t; }" : "=r"(a) : "l"(p));
    return a;
}
#define CP_ASYNC16(dst, src) asm volatile("cp.async.cg.shared.global [%0], [%1], 16;" :: "r"(dst), "l"(src) : "memory")
#define CP_COMMIT()          asm volatile("cp.async.commit_group;" ::: "memory")
#define CP_WAIT(n)           asm volatile("cp.async.wait_group %0;" :: "n"(n) : "memory")

__device__ __forceinline__ void ldsm4(uint32_t* r, uint32_t addr) {
    asm volatile("ldmatrix.sync.aligned.m8n8.x4.shared.b16 {%0,%1,%2,%3}, [%4];"
                 : "=r"(r[0]), "=r"(r[1]), "=r"(r[2]), "=r"(r[3]) : "r"(addr));
}
__device__ __forceinline__ void mma_f16(float* c, const uint32_t* a, const uint32_t* b) {
    asm volatile("mma.sync.aligned.m16n8k16.row.col.f32.f16.f16.f32 "
                 "{%0,%1,%2,%3}, {%4,%5,%6,%7}, {%8,%9}, {%0,%1,%2,%3};"
                 : "+f"(c[0]), "+f"(c[1]), "+f"(c[2]), "+f"(c[3])
                 : "r"(a[0]), "r"(a[1]), "r"(a[2]), "r"(a[3]), "r"(b[0]), "r"(b[1]));
}
__device__ __forceinline__ float tanh_ap(float x) {
    float r;
    asm("tanh.approx.f32 %0, %1;" : "=f"(r) : "f"(x));
    return r;
}

// ---------------- P1/P2/P3: tiny weight precompute --------------------
__global__ void k_p1(const float* __restrict__ W_qkv, const float* __restrict__ W_fc,
                     const float* __restrict__ b_qkv) {
    int d = threadIdx.x;
    float acc = 0.f;
    for (int e = 0; e < DD; e++) acc += W_qkv[d * 3 * DD + 2 * DD + e] * W_fc[e];
    g_wvfc[d] = acc;
    if (d == 0) {
        float b = 0.f;
        for (int e = 0; e < DD; e++) b += b_qkv[2 * DD + e] * W_fc[e];
        g_bu_p = b;
    }
}
// fused weight: W_token@W_qkv[:, :256], stored TRANSPOSED fp16
__global__ void k_p2(const float* __restrict__ W_token, const float* __restrict__ W_qkv) {
    __shared__ float wt[DD];
    int t = blockIdx.x, n = threadIdx.x;
    if (n < DD) wt[n] = W_token[t * DD + n];
    __syncthreads();
    float acc = 0.f;
    for (int d = 0; d < DD; d++) acc += wt[d] * W_qkv[d * 3 * DD + n];
    g_wTh[n * INDIM + t] = __float2half_rn(acc);
    if (n == 0) {
        float a = 0.f;
        for (int d = 0; d < DD; d++) a += wt[d] * g_wvfc[d];
        g_wu[t] = a;
    }
}
__global__ void k_p3(const float* __restrict__ b_token, const float* __restrict__ W_qkv,
                     const float* __restrict__ b_qkv) {
    int n = threadIdx.x;
    float acc = 0.f;
    for (int d = 0; d < DD; d++) acc += b_token[d] * W_qkv[d * 3 * DD + n];
    g_bqk[n] = acc + b_qkv[n];
    if (n == 0) {
        float a = 0.f;
        for (int d = 0; d < DD; d++) a += b_token[d] * g_wvfc[d];
        g_bu = a + g_bu_p;
    }
}

// ---------------- x -> fp16 split + u matvec (one warp per row) --------
__global__ __launch_bounds__(256) void k_xu(const float* __restrict__ x) {
    int row = blockIdx.x * 8 + (threadIdx.x >> 5);
    int lane = threadIdx.x & 31;
    const float* xr = x + (long)row * INDIM;
    __half* xh = g_xhi + (long)row * INDIM;
    float acc = 0.f;
#pragma unroll
    for (int i = 0; i < 6; i++) {
        int c = i * 128 + lane * 4;
        float4 v = *(const float4*)(xr + c);
        float4 wv = *(const float4*)(g_wu + c);
        acc += v.x * wv.x + v.y * wv.y + v.z * wv.z + v.w * wv.w;
        *(__half2*)(xh + c) = __floats2half2_rn(v.x, v.y);
        *(__half2*)(xh + c + 2) = __floats2half2_rn(v.z, v.w);
    }
#pragma unroll
    for (int off = 16; off; off >>= 1) acc += __shfl_xor_sync(0xFFFFFFFFu, acc, off);
    if (lane == 0) g_u[row] = 0.5f * (acc + g_bu);
}

// ---------------- projection GEMM (HMMA fp16, 1 pass per half) ---------
// BM=128, BN=128, BK=64. Stage: [xh 16K][wh 16K], double buffered.
// launch_bounds(.,2): two CTAs co-resident per SM to kill wave quantization.
#define PJ_STG  32768
#define PJ_SMEM (2 * PJ_STG)
__global__ __launch_bounds__(256, 2) void k_projh() {
    extern __shared__ char smem[];
    uint32_t sb = smem_u32(smem);
    int tid = threadIdx.x, lane = tid & 31, w = tid >> 5;
    int row0 = blockIdx.x * 128;
    int half = blockIdx.y;
    const __half* wh = g_wTh + (long)half * 128 * INDIM;

#define PJ_LOAD(buf, kc)                                                          \
    do {                                                                          \
        uint32_t base_ = sb + (buf) * PJ_STG;                                     \
        _Pragma("unroll")                                                         \
        for (int t_ = 0; t_ < 4; t_++) {                                          \
            int idx_ = t_ * 256 + tid;                                            \
            int r_ = idx_ >> 3, cu_ = idx_ & 7;                                   \
            uint32_t off_ = (uint32_t)r_ * 128u + (uint32_t)((cu_ ^ (r_ & 7)) << 4); \
            CP_ASYNC16(base_ + off_,         g_xhi + (long)(row0 + r_) * INDIM + (kc) + cu_ * 8); \
            CP_ASYNC16(base_ + 16384 + off_, wh + (long)r_ * INDIM + (kc) + cu_ * 8); \
        }                                                                         \
        CP_COMMIT();                                                              \
    } while (0)

    PJ_LOAD(0, 0);

    float acc[16][4];
#pragma unroll
    for (int nb = 0; nb < 16; nb++) {
        acc[nb][0] = 0.f; acc[nb][1] = 0.f; acc[nb][2] = 0.f; acc[nb][3] = 0.f;
    }

    int rA = 16 * w + (lane & 15);
    int cuA = lane >> 4;
    uint32_t rbA = (uint32_t)rA * 128u;
    int xA = rA & 7;
    int rB = (lane & 7) + ((lane & 16) >> 1);
    int cB = (lane >> 3) & 1;
    uint32_t uB = (uint32_t)rB * 128u;
    int xB = rB & 7;

    for (int s = 0; s < 12; s++) {
        if (s + 1 < 12) {
            PJ_LOAD((s + 1) & 1, (s + 1) * 64);
            CP_WAIT(1);
        } else {
            CP_WAIT(0);
        }
        __syncthreads();
        uint32_t base = sb + (s & 1) * PJ_STG;
#pragma unroll
        for (int kk = 0; kk < 4; kk++) {
            uint32_t Ah[4];
            uint32_t aoff = rbA + (uint32_t)(((kk * 2 + cuA) ^ xA) << 4);
            ldsm4(Ah, base + aoff);
            uint32_t coff = (uint32_t)(((kk * 2 + cB) ^ xB) << 4);
            uint32_t bh[8][4];
#pragma unroll
            for (int p = 0; p < 8; p++) ldsm4(bh[p], base + 16384 + p * 2048 + uB + coff);
#pragma unroll
            for (int p = 0; p < 8; p++) {
                mma_f16(acc[2 * p], Ah, &bh[p][0]);
                mma_f16(acc[2 * p + 1], Ah, &bh[p][2]);
            }
        }
        __syncthreads();
    }

    __half* dst = half ? g_kf : g_qf;
    int r0 = row0 + 16 * w + (lane >> 2);
#pragma unroll
    for (int nb = 0; nb < 16; nb++) {
        int c = nb * 8 + (lane & 3) * 2;
        float b0 = g_bqk[half * 128 + c];
        float b1 = g_bqk[half * 128 + c + 1];
        *(__half2*)(dst + (long)r0 * DD + c) = __floats2half2_rn(acc[nb][0] + b0, acc[nb][1] + b1);
        *(__half2*)(dst + (long)(r0 + 8) * DD + c) = __floats2half2_rn(acc[nb][2] + b0, acc[nb][3] + b1);
    }
}

// ---------------- out = b_fc (attention accumulates atomically) --------
__global__ void k_zero(const float* __restrict__ b_fc, float* __restrict__ out) {
    out[blockIdx.x * 256 + threadIdx.x] = b_fc[0];
}

// ---------------- attention: persistent, pipelined epilogue -----------
// Ping-pong accumulators: epilogue (tanh+fma) of item i is interleaved into
// the MMA kk-loop of item i+1 so MUFU overlaps the tensor pipe.
// K double buffered (2x32KB); u triple buffered (3x512B).
#define KBUF   32768
#define SO_US  65536
#define AT_SMEM (SO_US + 1536)

__global__ __launch_bounds__(256, 1) void k_attn(float* __restrict__ out) {
    extern __shared__ char smem[];
    uint32_t sb = smem_u32(smem);
    int tid = threadIdx.x, lane = tid & 31, w = tid >> 5;

    int start = (int)((long)blockIdx.x * NITEMS / gridDim.x);
    int end = (int)((long)(blockIdx.x + 1) * NITEMS / gridDim.x);

    int rB = (lane & 7) + ((lane & 16) >> 1);
    int cB = (lane >> 3) & 1;
    uint32_t uB = (uint32_t)rB * 256u;
    int xB = rB & 7;
    const int cl = (lane & 3) * 2;

    uint32_t Ah[8][4];
    float accA[16][4], accB[16][4];
    float o0 = 0.f, o1 = 0.f;
    int oit = -1, qit = -1;

#define PREFETCH(I)                                                             \
    do {                                                                        \
        int jn_ = (I) & (NJT - 1);                                              \
        uint32_t kb_ = sb + (((I) - start) & 1) * KBUF;                         \
        const __half* sh_ = g_kf + (long)jn_ * BN * DD;                         \
        _Pragma("unroll")                                                       \
        for (int t_ = 0; t_ < 8; t_++) {                                        \
            int i2_ = t_ * 256 + tid;                                           \
            int r_ = i2_ >> 4, cu_ = i2_ & 15;                                  \
            uint32_t off_ = (uint32_t)r_ * 256u + (uint32_t)((cu_ ^ (r_ & 7)) << 4); \
            CP_ASYNC16(kb_ + off_, sh_ + (long)r_ * DD + cu_ * 8);              \
        }                                                                       \
        if (tid < 32)                                                           \
            CP_ASYNC16(sb + SO_US + (((I) - start) % 3) * 512 + tid * 16,       \
                       g_u + jn_ * BN + tid * 4);                               \
        CP_COMMIT();                                                            \
    } while (0)

#define FLUSH()                                                                 \
    do {                                                                        \
        o0 += __shfl_xor_sync(0xFFFFFFFFu, o0, 1);                              \
        o0 += __shfl_xor_sync(0xFFFFFFFFu, o0, 2);                              \
        o1 += __shfl_xor_sync(0xFFFFFFFFu, o1, 1);                              \
        o1 += __shfl_xor_sync(0xFFFFFFFFu, o1, 2);                              \
        if ((lane & 3) == 0) {                                                  \
            int r_ = oit * 128 + 16 * w + (lane >> 2);                          \
            atomicAdd(out + r_, o0);                                            \
            atomicAdd(out + r_ + 8, o1);                                        \
        }                                                                       \
    } while (0)

// MMA for item I into ACC; epilogue of item EPI_I (in ACCP) interleaved per kk.
// DO_EPI must be a literal 0/1.
#define MMA_TILE(ACC, ACCP, I, DO_EPI, EPI_I)                                   \
    do {                                                                        \
        if (((I) >> 7) != qit) {                                                \
            qit = (I) >> 7;                                                     \
            const __half* qb_ = g_qf + ((long)qit * 128 + 16 * w + (lane >> 2)) * DD + cl; \
            _Pragma("unroll")                                                   \
            for (int kk = 0; kk < 8; kk++) {                                    \
                Ah[kk][0] = *(const uint32_t*)(qb_ + kk * 16);                  \
                Ah[kk][1] = *(const uint32_t*)(qb_ + 8 * DD + kk * 16);         \
                Ah[kk][2] = *(const uint32_t*)(qb_ + kk * 16 + 8);              \
                Ah[kk][3] = *(const uint32_t*)(qb_ + 8 * DD + kk * 16 + 8);     \
            }                                                                   \
        }                                                                       \
        if (DO_EPI) {                                                           \
            int eit_ = (EPI_I) >> 7;                                            \
            if (eit_ != oit) {                                                  \
                if (oit >= 0) FLUSH();                                          \
                oit = eit_; o0 = 0.f; o1 = 0.f;                                 \
            }                                                                   \
        }                                                                       \
        _Pragma("unroll")                                                       \
        for (int nb = 0; nb < 16; nb++) {                                       \
            ACC[nb][0] = 0.f; ACC[nb][1] = 0.f; ACC[nb][2] = 0.f; ACC[nb][3] = 0.f; \
        }                                                                       \
        uint32_t kb_ = sb + (((I) - start) & 1) * KBUF;                         \
        _Pragma("unroll")                                                       \
        for (int kk = 0; kk < 8; kk++) {                                        \
            uint32_t coff_ = (uint32_t)(((kk * 2 + cB) ^ xB) << 4);             \
            uint32_t bh_[8][4];                                                 \
            _Pragma("unroll")                                                   \
            for (int p = 0; p < 8; p++) ldsm4(bh_[p], kb_ + p * 4096 + uB + coff_); \
            _Pragma("unroll")                                                   \
            for (int p = 0; p < 8; p++) {                                       \
                mma_f16(ACC[2 * p], Ah[kk], &bh_[p][0]);                        \
                mma_f16(ACC[2 * p + 1], Ah[kk], &bh_[p][2]);                    \
            }                                                                   \
            if (DO_EPI) {                                                       \
                const float* Us_ = (const float*)(smem + SO_US +                \
                    ((((EPI_I) - start) % 3)) * 512);                           \
                _Pragma("unroll")                                               \
                for (int q2 = 0; q2 < 2; q2++) {                                \
                    int nb_ = kk * 2 + q2;                                      \
                    float2 u2_ = *(const float2*)(Us_ + nb_ * 8 + cl);          \
                    float t0_ = tanh_ap(0.5f * ACCP[nb_][0]);                   \
                    float t1_ = tanh_ap(0.5f * ACCP[nb_][1]);                   \
                    float t2_ = tanh_ap(0.5f * ACCP[nb_][2]);                   \
                    float t3_ = tanh_ap(0.5f * ACCP[nb_][3]);                   \
                    o0 += u2_.x + u2_.y; o1 += u2_.x + u2_.y;                   \
                    o0 = fmaf(t0_, u2_.x, o0); o0 = fmaf(t1_, u2_.y, o0);       \
                    o1 = fmaf(t2_, u2_.x, o1); o1 = fmaf(t3_, u2_.y, o1);       \
                }                                                               \
            }                                                                   \
        }                                                                       \
    } while (0)

#define EPI_FULL(ACCP, EPI_I)                                                   \
    do {                                                                        \
        int eit_ = (EPI_I) >> 7;                                                \
        if (eit_ != oit) {                                                      \
            if (oit >= 0) FLUSH();                                              \
            oit = eit_; o0 = 0.f; o1 = 0.f;                                     \
        }                                                                       \
        const float* Us_ = (const float*)(smem + SO_US + (((EPI_I) - start) % 3) * 512); \
        _Pragma("unroll")                                                       \
        for (int nb = 0; nb < 16; nb++) {                                       \
            float2 u2_ = *(const float2*)(Us_ + nb * 8 + cl);                   \
            float t0_ = tanh_ap(0.5f * ACCP[nb][0]);                            \
            float t1_ = tanh_ap(0.5f * ACCP[nb][1]);                            \
            float t2_ = tanh_ap(0.5f * ACCP[nb][2]);                            \
            float t3_ = tanh_ap(0.5f * ACCP[nb][3]);                            \
            o0 += u2_.x + u2_.y; o1 += u2_.x + u2_.y;                           \
            o0 = fmaf(t0_, u2_.x, o0); o0 = fmaf(t1_, u2_.y, o0);               \
            o1 = fmaf(t2_, u2_.x, o1); o1 = fmaf(t3_, u2_.y, o1);               \
        }                                                                       \
    } while (0)

    // preload item `start`
    PREFETCH(start);

    // peeled first iteration (no epilogue yet)
    {
        __syncthreads();
        if (start + 1 < end) {
            PREFETCH(start + 1);
            CP_WAIT(1);
        } else {
            CP_WAIT(0);
        }
        __syncthreads();
        MMA_TILE(accA, accB, start, 0, start);
    }

    for (int i = start + 1; i < end; i++) {
        __syncthreads();
        if (i + 1 < end) {
            PREFETCH(i + 1);
            CP_WAIT(1);
        } else {
            CP_WAIT(0);
        }
        __syncthreads();
        if ((i - start) & 1) {
            MMA_TILE(accB, accA, i, 1, i - 1);
        } else {
            MMA_TILE(accA, accB, i, 1, i - 1);
        }
    }

    // final epilogue for item end-1
    if ((end - 1 - start) & 1) {
        EPI_FULL(accB, end - 1);
    } else {
        EPI_FULL(accA, end - 1);
    }
    FLUSH();
}

// ---------------- launch ----------------------------------------------
extern "C" void kernel_launch(void* const* d_in, const int* in_sizes, int n_in,
                              void* d_out, int out_size) {
    const float* x       = (const float*)d_in[0];
    const float* W_token = (const float*)d_in[2];
    const float* b_token = (const float*)d_in[3];
    const float* W_qkv   = (const float*)d_in[4];
    const float* b_qkv   = (const float*)d_in[5];
    const float* W_fc    = (const float*)d_in[6];
    const float* b_fc    = (const float*)d_in[7];
    float* out = (float*)d_out;

    int nsm = 148;
    cudaDeviceGetAttribute(&nsm, cudaDevAttrMultiProcessorCount, 0);

    cudaFuncSetAttribute(k_attn, cudaFuncAttributeMaxDynamicSharedMemorySize, AT_SMEM);
    cudaFuncSetAttribute(k_projh, cudaFuncAttributeMaxDynamicSharedMemorySize, PJ_SMEM);

    k_p1<<<1, 128>>>(W_qkv, W_fc, b_qkv);
    k_p2<<<768, 256>>>(W_token, W_qkv);
    k_p3<<<1, 256>>>(b_token, W_qkv, b_qkv);
    k_xu<<<NROWS / 8, 256>>>(x);
    k_projh<<<dim3(128, 2), 256, PJ_SMEM>>>();
    k_zero<<<NROWS / 256, 256>>>(b_fc, out);
    k_attn<<<nsm, 256, AT_SMEM>>>(out);
}